// round 1
// baseline (speedup 1.0000x reference)
#include <cuda_runtime.h>
#include <cstdint>

#define NFE 256
#define NFC 128

// Scratch: 4 x [N,256] fp32 buffers (N=50000)
__device__ float g_Y1[(size_t)50000 * 256];
__device__ float g_A1[(size_t)50000 * 256];
__device__ float g_Y2[(size_t)50000 * 256];
__device__ float g_A2[(size_t)50000 * 256];

__device__ __forceinline__ float lrelu(float v) { return v > 0.f ? v : 0.2f * v; }

__global__ void zero_kernel(float4* __restrict__ a, float4* __restrict__ b, int n4) {
    int i = blockIdx.x * blockDim.x + threadIdx.x;
    if (i < n4) {
        float4 z = make_float4(0.f, 0.f, 0.f, 0.f);
        a[i] = z;
        b[i] = z;
    }
}

// GEMM: Y[row, 0:128] (+ colOff folded into Y ptr, row stride 256) = Amod @ B
// mode 0: Amod = where(A==0, me[k], A)                      (layer-1 input fix)
// mode 1: Amod = lrelu((2+eps)*A + Aadd + bvec[k])          (layer-2 fused input)
__global__ __launch_bounds__(256) void gemm_kernel(
    const float* __restrict__ A, const float* __restrict__ Aadd,
    const float* __restrict__ bvec, const float* __restrict__ epsp,
    const float* __restrict__ me,
    const float* __restrict__ B, float* __restrict__ Y,
    int M, int K, int lda, int mode)
{
    __shared__ float As[16][132];
    __shared__ float Bs[16][128];
    const int tid = threadIdx.x;
    const int rowBase = blockIdx.x * 128;
    const int ty = tid >> 4;
    const int tx = tid & 15;
    float eps2 = 0.f;
    if (mode == 1) eps2 = 2.0f + *epsp;

    float acc[8][8];
#pragma unroll
    for (int i = 0; i < 8; i++)
#pragma unroll
        for (int j = 0; j < 8; j++) acc[i][j] = 0.f;

    for (int k0 = 0; k0 < K; k0 += 16) {
        // A tile: 128 rows x 16 k
#pragma unroll
        for (int it = 0; it < 2; it++) {
            int idx = tid + it * 256;          // 0..511
            int r = idx >> 2;                  // 0..127
            int kq = (idx & 3) << 2;           // 0,4,8,12
            int grow = rowBase + r;
            float4 v = make_float4(0.f, 0.f, 0.f, 0.f);
            if (grow < M) {
                v = *(const float4*)(A + (size_t)grow * lda + k0 + kq);
                if (mode == 0) {
                    if (v.x == 0.f) v.x = me[k0 + kq + 0];
                    if (v.y == 0.f) v.y = me[k0 + kq + 1];
                    if (v.z == 0.f) v.z = me[k0 + kq + 2];
                    if (v.w == 0.f) v.w = me[k0 + kq + 3];
                } else {
                    float4 w = *(const float4*)(Aadd + (size_t)grow * lda + k0 + kq);
                    v.x = lrelu(v.x * eps2 + w.x + bvec[k0 + kq + 0]);
                    v.y = lrelu(v.y * eps2 + w.y + bvec[k0 + kq + 1]);
                    v.z = lrelu(v.z * eps2 + w.z + bvec[k0 + kq + 2]);
                    v.w = lrelu(v.w * eps2 + w.w + bvec[k0 + kq + 3]);
                }
            }
            As[kq + 0][r] = v.x;
            As[kq + 1][r] = v.y;
            As[kq + 2][r] = v.z;
            As[kq + 3][r] = v.w;
        }
        // B tile: 16 k x 128 n  (B is row-major [K,128])
#pragma unroll
        for (int it = 0; it < 2; it++) {
            int idx = tid + it * 256;
            int kr = idx >> 5;                 // 0..15
            int c4 = (idx & 31) << 2;          // 0..124
            *(float4*)&Bs[kr][c4] = *(const float4*)(B + (size_t)(k0 + kr) * 128 + c4);
        }
        __syncthreads();
#pragma unroll
        for (int k = 0; k < 16; k++) {
            float4 a0 = *(const float4*)&As[k][ty * 8];
            float4 a1 = *(const float4*)&As[k][ty * 8 + 4];
            float4 b0 = *(const float4*)&Bs[k][tx * 8];
            float4 b1 = *(const float4*)&Bs[k][tx * 8 + 4];
            float av[8] = {a0.x, a0.y, a0.z, a0.w, a1.x, a1.y, a1.z, a1.w};
            float bv[8] = {b0.x, b0.y, b0.z, b0.w, b1.x, b1.y, b1.z, b1.w};
#pragma unroll
            for (int i = 0; i < 8; i++)
#pragma unroll
                for (int j = 0; j < 8; j++) acc[i][j] += av[i] * bv[j];
        }
        __syncthreads();
    }
#pragma unroll
    for (int i = 0; i < 8; i++) {
        int grow = rowBase + ty * 8 + i;
        if (grow < M) {
            float* p = Y + (size_t)grow * 256 + tx * 8;
            float4 o0 = make_float4(acc[i][0], acc[i][1], acc[i][2], acc[i][3]);
            float4 o1 = make_float4(acc[i][4], acc[i][5], acc[i][6], acc[i][7]);
            *(float4*)p = o0;
            *(float4*)(p + 4) = o1;
        }
    }
}

// Edge scatter: for each edge e, Agg[dst[e], :] += Y[src[e], :]  (256 floats, 64 float4 lanes)
__global__ void scatter_kernel(const float* __restrict__ Y, float* __restrict__ Agg,
                               const int* __restrict__ ei, int E)
{
    long long gid = (long long)blockIdx.x * blockDim.x + threadIdx.x;
    long long total = (long long)E * 64;
    if (gid >= total) return;
    int e = (int)(gid >> 6);
    int q = ((int)gid & 63) << 2;
    int s = __ldg(ei + e);
    int d = __ldg(ei + E + e);
    float4 v = *(const float4*)(Y + (size_t)s * 256 + q);
    float* pd = Agg + (size_t)d * 256 + q;
    asm volatile("red.global.add.v4.f32 [%0], {%1, %2, %3, %4};"
                 :: "l"(pd), "f"(v.x), "f"(v.y), "f"(v.z), "f"(v.w) : "memory");
}

// Per-node head: h = lrelu((2+eps2)*Y2 + A2 + b2);  out = lrelu(h @ Wm + bm)
// one warp per node; lane handles 8 contiguous features
__global__ __launch_bounds__(256) void out_kernel(
    const float* __restrict__ Y2, const float* __restrict__ A2,
    const float* __restrict__ b2e, const float* __restrict__ b2c,
    const float* __restrict__ e2e, const float* __restrict__ e2c,
    const float* __restrict__ Wm, const float* __restrict__ bm,
    float* __restrict__ out, int M)
{
    __shared__ float sW[2048];
    __shared__ float sb[8];
    for (int i = threadIdx.x; i < 2048; i += 256) sW[i] = Wm[i];
    if (threadIdx.x < 8) sb[threadIdx.x] = bm[threadIdx.x];
    __syncthreads();

    int gwarp = (blockIdx.x * 256 + threadIdx.x) >> 5;
    int lane = threadIdx.x & 31;
    if (gwarp >= M) return;

    float f2e = 2.f + *e2e;
    float f2c = 2.f + *e2c;
    int j0 = lane * 8;
    float fac = (j0 < 128) ? f2e : f2c;
    const float* bb = (j0 < 128) ? (b2e + j0) : (b2c + (j0 - 128));
    size_t base = (size_t)gwarp * 256 + j0;

    float acc[8];
#pragma unroll
    for (int n = 0; n < 8; n++) acc[n] = 0.f;

#pragma unroll
    for (int jj = 0; jj < 8; jj += 4) {
        float4 y = *(const float4*)(Y2 + base + jj);
        float4 a = *(const float4*)(A2 + base + jj);
        float h0 = lrelu(y.x * fac + a.x + bb[jj + 0]);
        float h1 = lrelu(y.y * fac + a.y + bb[jj + 1]);
        float h2 = lrelu(y.z * fac + a.z + bb[jj + 2]);
        float h3 = lrelu(y.w * fac + a.w + bb[jj + 3]);
        const float* w = &sW[(size_t)(j0 + jj) * 8];
#pragma unroll
        for (int n = 0; n < 8; n++)
            acc[n] += h0 * w[n] + h1 * w[8 + n] + h2 * w[16 + n] + h3 * w[24 + n];
    }
#pragma unroll
    for (int off = 16; off >= 1; off >>= 1)
#pragma unroll
        for (int n = 0; n < 8; n++)
            acc[n] += __shfl_xor_sync(0xffffffffu, acc[n], off);
    if (lane == 0) {
#pragma unroll
        for (int n = 0; n < 8; n++)
            out[(size_t)gwarp * 8 + n] = lrelu(acc[n] + sb[n]);
    }
}

// central MLP: logits = relu(out[cidx] @ Wp1 + bp1) @ Wp2 + bp2
__global__ __launch_bounds__(256) void central_kernel(
    const float* __restrict__ out, const int* __restrict__ cidx,
    const float* __restrict__ Wp1, const float* __restrict__ bp1,
    const float* __restrict__ Wp2, const float* __restrict__ bp2,
    float* __restrict__ logits, int C)
{
    __shared__ float s1[1024];
    __shared__ float sb1[128];
    __shared__ float s2[1024];
    __shared__ float sb2[8];
    for (int i = threadIdx.x; i < 1024; i += 256) { s1[i] = Wp1[i]; s2[i] = Wp2[i]; }
    if (threadIdx.x < 128) sb1[threadIdx.x] = bp1[threadIdx.x];
    if (threadIdx.x < 8) sb2[threadIdx.x] = bp2[threadIdx.x];
    __syncthreads();

    int t = blockIdx.x * 256 + threadIdx.x;
    if (t >= C) return;
    int ci = cidx[t];
    float g[8];
#pragma unroll
    for (int k = 0; k < 8; k++) g[k] = out[(size_t)ci * 8 + k];
    float acc[8];
#pragma unroll
    for (int m = 0; m < 8; m++) acc[m] = sb2[m];
    for (int n = 0; n < 128; n++) {
        float tn = sb1[n];
#pragma unroll
        for (int k = 0; k < 8; k++) tn += g[k] * s1[k * 128 + n];
        tn = fmaxf(tn, 0.f);
#pragma unroll
        for (int m = 0; m < 8; m++) acc[m] += tn * s2[n * 8 + m];
    }
#pragma unroll
    for (int m = 0; m < 8; m++) logits[(size_t)t * 8 + m] = acc[m];
}

extern "C" void kernel_launch(void* const* d_in, const int* in_sizes, int n_in,
                              void* d_out, int out_size)
{
    const float* x    = (const float*)d_in[0];
    const float* c    = (const float*)d_in[1];
    const int*   ei   = (const int*)d_in[2];
    const int*   cidx = (const int*)d_in[3];
    const float* me_x = (const float*)d_in[4];
    const float* me_c = (const float*)d_in[5];
    const float* W1e  = (const float*)d_in[6];
    const float* b1e  = (const float*)d_in[7];
    const float* e1e  = (const float*)d_in[8];
    const float* W2e  = (const float*)d_in[9];
    const float* b2e  = (const float*)d_in[10];
    const float* e2e  = (const float*)d_in[11];
    const float* W1c  = (const float*)d_in[12];
    const float* b1c  = (const float*)d_in[13];
    const float* e1c  = (const float*)d_in[14];
    const float* W2c  = (const float*)d_in[15];
    const float* b2c  = (const float*)d_in[16];
    const float* e2c  = (const float*)d_in[17];
    const float* Wm   = (const float*)d_in[18];
    const float* bm   = (const float*)d_in[19];
    const float* Wp1  = (const float*)d_in[20];
    const float* bp1  = (const float*)d_in[21];
    const float* Wp2  = (const float*)d_in[22];
    const float* bp2  = (const float*)d_in[23];

    const int Nn = in_sizes[0] / NFE;       // 50000
    const int E  = in_sizes[2] / 2;         // 800000
    const int C  = in_sizes[3];             // 512

    float *Y1, *A1, *Y2, *A2;
    cudaGetSymbolAddress((void**)&Y1, g_Y1);
    cudaGetSymbolAddress((void**)&A1, g_A1);
    cudaGetSymbolAddress((void**)&Y2, g_Y2);
    cudaGetSymbolAddress((void**)&A2, g_A2);

    float* out_p    = (float*)d_out;              // [N, 8]
    float* logits_p = (float*)d_out + (size_t)Nn * 8;

    // zero aggregation buffers
    {
        int n4 = Nn * 256 / 4;
        zero_kernel<<<(n4 + 255) / 256, 256>>>((float4*)A1, (float4*)A2, n4);
    }

    int gridM = (Nn + 127) / 128;

    // layer-1 projections (matmul-first): Y1[:,0:128]=fix(x)@W1e, Y1[:,128:256]=fix(c)@W1c
    gemm_kernel<<<gridM, 256>>>(x, nullptr, nullptr, e1e, me_x, W1e, Y1, Nn, NFE, NFE, 0);
    gemm_kernel<<<gridM, 256>>>(c, nullptr, nullptr, e1c, me_c, W1c, Y1 + 128, Nn, NFC, NFC, 0);

    // layer-1 aggregation
    {
        long long total = (long long)E * 64;
        int blocks = (int)((total + 255) / 256);
        scatter_kernel<<<blocks, 256>>>(Y1, A1, ei, E);
    }

    // layer-2 projections with fused layer-1 epilogue in A-load
    gemm_kernel<<<gridM, 256>>>(Y1, A1, b1e, e1e, nullptr, W2e, Y2, Nn, 128, 256, 1);
    gemm_kernel<<<gridM, 256>>>(Y1 + 128, A1 + 128, b1c, e1c, nullptr, W2c, Y2 + 128, Nn, 128, 256, 1);

    // layer-2 aggregation
    {
        long long total = (long long)E * 64;
        int blocks = (int)((total + 255) / 256);
        scatter_kernel<<<blocks, 256>>>(Y2, A2, ei, E);
    }

    // output head
    {
        int blocks = (Nn * 32 + 255) / 256;
        out_kernel<<<blocks, 256>>>(Y2, A2, b2e, b2c, e2e, e2c, Wm, bm, out_p, Nn);
    }

    // central MLP
    central_kernel<<<(C + 255) / 256, 256>>>(out_p, cidx, Wp1, bp1, Wp2, bp2, logits_p, C);
}

// round 2
// speedup vs baseline: 1.2304x; 1.2304x over previous
#include <cuda_runtime.h>
#include <cstdint>

#define NFE 256
#define NFC 128
#define MAXN 50000
#define MAXE 800000

// Scratch buffers
__device__ float g_Y1[(size_t)MAXN * 256];
__device__ float g_H1[(size_t)MAXN * 256];
__device__ float g_Y2[(size_t)MAXN * 256];
__device__ float g_H2[(size_t)MAXN * 256];
__device__ int g_cnt[MAXN];
__device__ int g_fill[MAXN];
__device__ int g_rowptr[MAXN + 1];
__device__ int g_csrc[MAXE];

__device__ __forceinline__ float lrelu(float v) { return v > 0.f ? v : 0.2f * v; }

// ---------------- CSR build ----------------
__global__ void zero_cnt_kernel(int n) {
    int i = blockIdx.x * blockDim.x + threadIdx.x;
    if (i < n) g_cnt[i] = 0;
}

__global__ void hist_kernel(const int* __restrict__ ei, int E) {
    int e = blockIdx.x * blockDim.x + threadIdx.x;
    if (e < E) atomicAdd(&g_cnt[ei[E + e]], 1);
}

__global__ __launch_bounds__(1024) void scan_kernel(int N) {
    __shared__ int ssum[1024];
    int tid = threadIdx.x;
    int chunk = (N + 1023) / 1024;
    int lo = tid * chunk;
    int hi = lo + chunk;
    if (hi > N) hi = N;
    int s = 0;
    for (int i = lo; i < hi; i++) s += g_cnt[i];
    ssum[tid] = s;
    __syncthreads();
    // Hillis-Steele inclusive scan
    for (int off = 1; off < 1024; off <<= 1) {
        int t = (tid >= off) ? ssum[tid - off] : 0;
        __syncthreads();
        ssum[tid] += t;
        __syncthreads();
    }
    int run = ssum[tid] - s;  // exclusive prefix for this chunk
    for (int i = lo; i < hi; i++) {
        g_rowptr[i] = run;
        g_fill[i] = run;
        run += g_cnt[i];
    }
    if (tid == 1023) g_rowptr[N] = ssum[1023];
}

__global__ void fill_kernel(const int* __restrict__ ei, int E) {
    int e = blockIdx.x * blockDim.x + threadIdx.x;
    if (e < E) {
        int s = ei[e];
        int d = ei[E + e];
        int pos = atomicAdd(&g_fill[d], 1);
        g_csrc[pos] = s;
    }
}

// ---------------- GEMM ----------------
// Y[row, 0:128] (colOff folded into Y ptr; Y row stride 256) = Amod @ B
// mode 0: Amod = where(A==0, me[k], A)
// mode 2: Amod = A (plain)
__global__ __launch_bounds__(256) void gemm_kernel(
    const float* __restrict__ A, const float* __restrict__ me,
    const float* __restrict__ B, float* __restrict__ Y,
    int M, int K, int lda, int mode)
{
    __shared__ float As[32][132];
    __shared__ float Bs[32][128];
    const int tid = threadIdx.x;
    const int rowBase = blockIdx.x * 128;
    const int ty = tid >> 4;
    const int tx = tid & 15;

    float acc[8][8];
#pragma unroll
    for (int i = 0; i < 8; i++)
#pragma unroll
        for (int j = 0; j < 8; j++) acc[i][j] = 0.f;

    for (int k0 = 0; k0 < K; k0 += 32) {
        // A tile: 128 rows x 32 k
#pragma unroll
        for (int it = 0; it < 4; it++) {
            int idx = tid + it * 256;          // 0..1023
            int r = idx >> 3;                  // 0..127
            int kq = (idx & 7) << 2;           // 0..28
            int grow = rowBase + r;
            float4 v = make_float4(0.f, 0.f, 0.f, 0.f);
            if (grow < M) {
                v = *(const float4*)(A + (size_t)grow * lda + k0 + kq);
                if (mode == 0) {
                    if (v.x == 0.f) v.x = me[k0 + kq + 0];
                    if (v.y == 0.f) v.y = me[k0 + kq + 1];
                    if (v.z == 0.f) v.z = me[k0 + kq + 2];
                    if (v.w == 0.f) v.w = me[k0 + kq + 3];
                }
            }
            As[kq + 0][r] = v.x;
            As[kq + 1][r] = v.y;
            As[kq + 2][r] = v.z;
            As[kq + 3][r] = v.w;
        }
        // B tile: 32 k x 128 n
#pragma unroll
        for (int it = 0; it < 4; it++) {
            int idx = tid + it * 256;
            int kr = idx >> 5;                 // 0..31
            int c4 = (idx & 31) << 2;          // 0..124
            *(float4*)&Bs[kr][c4] = *(const float4*)(B + (size_t)(k0 + kr) * 128 + c4);
        }
        __syncthreads();
#pragma unroll
        for (int k = 0; k < 32; k++) {
            float4 a0 = *(const float4*)&As[k][ty * 8];
            float4 a1 = *(const float4*)&As[k][ty * 8 + 4];
            float4 b0 = *(const float4*)&Bs[k][tx * 8];
            float4 b1 = *(const float4*)&Bs[k][tx * 8 + 4];
            float av[8] = {a0.x, a0.y, a0.z, a0.w, a1.x, a1.y, a1.z, a1.w};
            float bv[8] = {b0.x, b0.y, b0.z, b0.w, b1.x, b1.y, b1.z, b1.w};
#pragma unroll
            for (int i = 0; i < 8; i++)
#pragma unroll
                for (int j = 0; j < 8; j++) acc[i][j] += av[i] * bv[j];
        }
        __syncthreads();
    }
#pragma unroll
    for (int i = 0; i < 8; i++) {
        int grow = rowBase + ty * 8 + i;
        if (grow < M) {
            float* p = Y + (size_t)grow * 256 + tx * 8;
            *(float4*)p = make_float4(acc[i][0], acc[i][1], acc[i][2], acc[i][3]);
            *(float4*)(p + 4) = make_float4(acc[i][4], acc[i][5], acc[i][6], acc[i][7]);
        }
    }
}

// ---------------- CSR gather + fused GIN epilogue ----------------
// H[n] = lrelu((2+eps)*Y[n] + sum_{j in N(n)} Y[j] + b)   (per-half eps/b)
__global__ __launch_bounds__(256) void gather_kernel(
    const float* __restrict__ Y, float* __restrict__ H,
    const float* __restrict__ be, const float* __restrict__ bc,
    const float* __restrict__ epe, const float* __restrict__ epc, int Nn)
{
    const unsigned FULL = 0xffffffffu;
    int gwarp = (blockIdx.x * 256 + threadIdx.x) >> 5;
    int lane = threadIdx.x & 31;
    if (gwarp >= Nn) return;

    int beg = g_rowptr[gwarp];
    int end = g_rowptr[gwarp + 1];
    int j0 = lane * 8;

    float acc[8];
#pragma unroll
    for (int i = 0; i < 8; i++) acc[i] = 0.f;

    for (int base = beg; base < end; base += 32) {
        int idx = base + lane;
        int sl = (idx < end) ? g_csrc[idx] : 0;
        int cnt = end - base;
        if (cnt > 32) cnt = 32;
        int j = 0;
        for (; j + 1 < cnt; j += 2) {
            int s0 = __shfl_sync(FULL, sl, j);
            int s1 = __shfl_sync(FULL, sl, j + 1);
            const float* p0 = Y + (size_t)s0 * 256 + j0;
            const float* p1 = Y + (size_t)s1 * 256 + j0;
            float4 a0 = *(const float4*)p0;
            float4 a1 = *(const float4*)(p0 + 4);
            float4 c0 = *(const float4*)p1;
            float4 c1 = *(const float4*)(p1 + 4);
            acc[0] += a0.x + c0.x; acc[1] += a0.y + c0.y;
            acc[2] += a0.z + c0.z; acc[3] += a0.w + c0.w;
            acc[4] += a1.x + c1.x; acc[5] += a1.y + c1.y;
            acc[6] += a1.z + c1.z; acc[7] += a1.w + c1.w;
        }
        if (j < cnt) {
            int s0 = __shfl_sync(FULL, sl, j);
            const float* p0 = Y + (size_t)s0 * 256 + j0;
            float4 a0 = *(const float4*)p0;
            float4 a1 = *(const float4*)(p0 + 4);
            acc[0] += a0.x; acc[1] += a0.y; acc[2] += a0.z; acc[3] += a0.w;
            acc[4] += a1.x; acc[5] += a1.y; acc[6] += a1.z; acc[7] += a1.w;
        }
    }

    float fac;
    const float* bb;
    if (j0 < 128) { fac = 2.f + *epe; bb = be + j0; }
    else          { fac = 2.f + *epc; bb = bc + (j0 - 128); }

    const float* py = Y + (size_t)gwarp * 256 + j0;
    float4 y0 = *(const float4*)py;
    float4 y1 = *(const float4*)(py + 4);
    float4 o0, o1;
    o0.x = lrelu(fmaf(y0.x, fac, acc[0]) + bb[0]);
    o0.y = lrelu(fmaf(y0.y, fac, acc[1]) + bb[1]);
    o0.z = lrelu(fmaf(y0.z, fac, acc[2]) + bb[2]);
    o0.w = lrelu(fmaf(y0.w, fac, acc[3]) + bb[3]);
    o1.x = lrelu(fmaf(y1.x, fac, acc[4]) + bb[4]);
    o1.y = lrelu(fmaf(y1.y, fac, acc[5]) + bb[5]);
    o1.z = lrelu(fmaf(y1.z, fac, acc[6]) + bb[6]);
    o1.w = lrelu(fmaf(y1.w, fac, acc[7]) + bb[7]);
    float* ph = H + (size_t)gwarp * 256 + j0;
    *(float4*)ph = o0;
    *(float4*)(ph + 4) = o1;
}

// ---------------- output head ----------------
// out = lrelu(H @ Wm + bm)     H: [N,256], Wm: [256,8]
__global__ __launch_bounds__(256) void out_kernel(
    const float* __restrict__ H,
    const float* __restrict__ Wm, const float* __restrict__ bm,
    float* __restrict__ out, int M)
{
    __shared__ float sW[2048];
    __shared__ float sb[8];
    for (int i = threadIdx.x; i < 2048; i += 256) sW[i] = Wm[i];
    if (threadIdx.x < 8) sb[threadIdx.x] = bm[threadIdx.x];
    __syncthreads();

    int gwarp = (blockIdx.x * 256 + threadIdx.x) >> 5;
    int lane = threadIdx.x & 31;
    if (gwarp >= M) return;
    int j0 = lane * 8;
    const float* ph = H + (size_t)gwarp * 256 + j0;
    float4 h0 = *(const float4*)ph;
    float4 h1 = *(const float4*)(ph + 4);
    float hv[8] = {h0.x, h0.y, h0.z, h0.w, h1.x, h1.y, h1.z, h1.w};

    float acc[8];
#pragma unroll
    for (int n = 0; n < 8; n++) acc[n] = 0.f;
#pragma unroll
    for (int jj = 0; jj < 8; jj++) {
        const float* w = &sW[(size_t)(j0 + jj) * 8];
#pragma unroll
        for (int n = 0; n < 8; n++) acc[n] += hv[jj] * w[n];
    }
#pragma unroll
    for (int off = 16; off >= 1; off >>= 1)
#pragma unroll
        for (int n = 0; n < 8; n++)
            acc[n] += __shfl_xor_sync(0xffffffffu, acc[n], off);
    if (lane == 0) {
#pragma unroll
        for (int n = 0; n < 8; n++)
            out[(size_t)gwarp * 8 + n] = lrelu(acc[n] + sb[n]);
    }
}

// ---------------- central MLP ----------------
__global__ __launch_bounds__(256) void central_kernel(
    const float* __restrict__ out, const int* __restrict__ cidx,
    const float* __restrict__ Wp1, const float* __restrict__ bp1,
    const float* __restrict__ Wp2, const float* __restrict__ bp2,
    float* __restrict__ logits, int C)
{
    __shared__ float s1[1024];
    __shared__ float sb1[128];
    __shared__ float s2[1024];
    __shared__ float sb2[8];
    for (int i = threadIdx.x; i < 1024; i += 256) { s1[i] = Wp1[i]; s2[i] = Wp2[i]; }
    if (threadIdx.x < 128) sb1[threadIdx.x] = bp1[threadIdx.x];
    if (threadIdx.x < 8) sb2[threadIdx.x] = bp2[threadIdx.x];
    __syncthreads();

    int t = blockIdx.x * 256 + threadIdx.x;
    if (t >= C) return;
    int ci = cidx[t];
    float g[8];
#pragma unroll
    for (int k = 0; k < 8; k++) g[k] = out[(size_t)ci * 8 + k];
    float acc[8];
#pragma unroll
    for (int m = 0; m < 8; m++) acc[m] = sb2[m];
    for (int n = 0; n < 128; n++) {
        float tn = sb1[n];
#pragma unroll
        for (int k = 0; k < 8; k++) tn += g[k] * s1[k * 128 + n];
        tn = fmaxf(tn, 0.f);
#pragma unroll
        for (int m = 0; m < 8; m++) acc[m] += tn * s2[n * 8 + m];
    }
#pragma unroll
    for (int m = 0; m < 8; m++) logits[(size_t)t * 8 + m] = acc[m];
}

extern "C" void kernel_launch(void* const* d_in, const int* in_sizes, int n_in,
                              void* d_out, int out_size)
{
    const float* x    = (const float*)d_in[0];
    const float* c    = (const float*)d_in[1];
    const int*   ei   = (const int*)d_in[2];
    const int*   cidx = (const int*)d_in[3];
    const float* me_x = (const float*)d_in[4];
    const float* me_c = (const float*)d_in[5];
    const float* W1e  = (const float*)d_in[6];
    const float* b1e  = (const float*)d_in[7];
    const float* e1e  = (const float*)d_in[8];
    const float* W2e  = (const float*)d_in[9];
    const float* b2e  = (const float*)d_in[10];
    const float* e2e  = (const float*)d_in[11];
    const float* W1c  = (const float*)d_in[12];
    const float* b1c  = (const float*)d_in[13];
    const float* e1c  = (const float*)d_in[14];
    const float* W2c  = (const float*)d_in[15];
    const float* b2c  = (const float*)d_in[16];
    const float* e2c  = (const float*)d_in[17];
    const float* Wm   = (const float*)d_in[18];
    const float* bm   = (const float*)d_in[19];
    const float* Wp1  = (const float*)d_in[20];
    const float* bp1  = (const float*)d_in[21];
    const float* Wp2  = (const float*)d_in[22];
    const float* bp2  = (const float*)d_in[23];

    const int Nn = in_sizes[0] / NFE;       // 50000
    const int E  = in_sizes[2] / 2;         // 800000
    const int C  = in_sizes[3];             // 512

    float *Y1, *H1, *Y2, *H2;
    cudaGetSymbolAddress((void**)&Y1, g_Y1);
    cudaGetSymbolAddress((void**)&H1, g_H1);
    cudaGetSymbolAddress((void**)&Y2, g_Y2);
    cudaGetSymbolAddress((void**)&H2, g_H2);

    float* out_p    = (float*)d_out;              // [N, 8]
    float* logits_p = (float*)d_out + (size_t)Nn * 8;

    // CSR build (by dst)
    zero_cnt_kernel<<<(Nn + 255) / 256, 256>>>(Nn);
    hist_kernel<<<(E + 255) / 256, 256>>>(ei, E);
    scan_kernel<<<1, 1024>>>(Nn);
    fill_kernel<<<(E + 255) / 256, 256>>>(ei, E);

    int gridM = (Nn + 127) / 128;
    int gridW = (Nn * 32 + 255) / 256;

    // layer-1 projections (matmul-first)
    gemm_kernel<<<gridM, 256>>>(x, me_x, W1e, Y1, Nn, NFE, NFE, 0);
    gemm_kernel<<<gridM, 256>>>(c, me_c, W1c, Y1 + 128, Nn, NFC, NFC, 0);

    // layer-1 aggregation + epilogue -> H1
    gather_kernel<<<gridW, 256>>>(Y1, H1, b1e, b1c, e1e, e1c, Nn);

    // layer-2 projections (plain)
    gemm_kernel<<<gridM, 256>>>(H1, nullptr, W2e, Y2, Nn, 128, 256, 2);
    gemm_kernel<<<gridM, 256>>>(H1 + 128, nullptr, W2c, Y2 + 128, Nn, 128, 256, 2);

    // layer-2 aggregation + epilogue -> H2
    gather_kernel<<<gridW, 256>>>(Y2, H2, b2e, b2c, e2e, e2c, Nn);

    // output head
    out_kernel<<<gridW, 256>>>(H2, Wm, bm, out_p, Nn);

    // central MLP
    central_kernel<<<(C + 255) / 256, 256>>>(out_p, cidx, Wp1, bp1, Wp2, bp2, logits_p, C);
}

// round 3
// speedup vs baseline: 1.4063x; 1.1429x over previous
#include <cuda_runtime.h>
#include <cstdint>

#define NFE 256
#define NFC 128
#define MAXN 50000
#define MAXE 800000

// Scratch buffers
__device__ float g_Y1[(size_t)MAXN * 256];
__device__ float g_H1[(size_t)MAXN * 256];
__device__ float g_Y2[(size_t)MAXN * 256];
__device__ float g_H2[(size_t)MAXN * 256];
__device__ int g_cnt[MAXN];
__device__ int g_fill[MAXN];
__device__ int g_rowptr[MAXN + 1];
__device__ int g_csrc[MAXE];

__device__ __forceinline__ float lrelu(float v) { return v > 0.f ? v : 0.2f * v; }

__device__ __forceinline__ uint32_t f2tf(float x) {
    uint32_t u;
    asm("cvt.rna.tf32.f32 %0, %1;" : "=r"(u) : "f"(x));
    return u;
}

// ---------------- CSR build ----------------
__global__ void zero_cnt_kernel(int n) {
    int i = blockIdx.x * blockDim.x + threadIdx.x;
    if (i < n) g_cnt[i] = 0;
}

__global__ void hist_kernel(const int* __restrict__ ei, int E) {
    int e = blockIdx.x * blockDim.x + threadIdx.x;
    if (e < E) atomicAdd(&g_cnt[ei[E + e]], 1);
}

__global__ __launch_bounds__(1024) void scan_kernel(int N) {
    __shared__ int ssum[1024];
    int tid = threadIdx.x;
    int chunk = (N + 1023) / 1024;
    int lo = tid * chunk;
    int hi = lo + chunk;
    if (hi > N) hi = N;
    int s = 0;
    for (int i = lo; i < hi; i++) s += g_cnt[i];
    ssum[tid] = s;
    __syncthreads();
    for (int off = 1; off < 1024; off <<= 1) {
        int t = (tid >= off) ? ssum[tid - off] : 0;
        __syncthreads();
        ssum[tid] += t;
        __syncthreads();
    }
    int run = ssum[tid] - s;
    for (int i = lo; i < hi; i++) {
        g_rowptr[i] = run;
        g_fill[i] = run;
        run += g_cnt[i];
    }
    if (tid == 1023) g_rowptr[N] = ssum[1023];
}

__global__ void fill_kernel(const int* __restrict__ ei, int E) {
    int e = blockIdx.x * blockDim.x + threadIdx.x;
    if (e < E) {
        int s = ei[e];
        int d = ei[E + e];
        int pos = atomicAdd(&g_fill[d], 1);
        g_csrc[pos] = s;
    }
}

// ---------------- TF32x3 tensor-core GEMM ----------------
// Y[rows, 0:128] (col offset folded into Y; Y row stride 256) = Amod @ B
// mode 0: Amod = where(A==0, me[k], A);  mode 2: Amod = A
#define MMA_OP(D, Areg, B0, B1)                                             \
    asm volatile("mma.sync.aligned.m16n8k8.row.col.f32.tf32.tf32.f32 "      \
                 "{%0,%1,%2,%3},{%4,%5,%6,%7},{%8,%9},{%0,%1,%2,%3};"       \
                 : "+f"(D[0]), "+f"(D[1]), "+f"(D[2]), "+f"(D[3])           \
                 : "r"(Areg[0]), "r"(Areg[1]), "r"(Areg[2]), "r"(Areg[3]),  \
                   "r"(B0), "r"(B1))

__global__ __launch_bounds__(256, 2) void gemm_tf32_kernel(
    const float* __restrict__ A, const float* __restrict__ me,
    const float* __restrict__ B, float* __restrict__ Y,
    int M, int K, int lda, int mode)
{
    __shared__ uint32_t Ahi[128][20], Alo[128][20];   // KC=16 + pad4
    __shared__ uint32_t Bhi[16][136], Blo[16][136];   // 128 + pad8

    const int tid = threadIdx.x;
    const int lane = tid & 31;
    const int warp = tid >> 5;
    const int wr = warp & 1;    // warp row
    const int wc = warp >> 1;   // warp col
    const int rowBase = blockIdx.x * 128;

    float d[4][4][4];
#pragma unroll
    for (int m = 0; m < 4; m++)
#pragma unroll
        for (int n = 0; n < 4; n++)
#pragma unroll
            for (int r = 0; r < 4; r++) d[m][n][r] = 0.f;

    // per-thread load coords
    const int a_row = tid >> 2;             // first A row (0..63), +64 on it=1
    const int a_q = (tid & 3) << 2;         // A k quad
    const int b_kr = tid >> 5;              // first B k row (0..7), +8 on it=1
    const int b_c4 = (lane) << 2;           // B col quad (0..124)

    float4 pa[2], pb[2];

    auto prefetch = [&](int k0) {
#pragma unroll
        for (int it = 0; it < 2; it++) {
            int grow = rowBase + a_row + it * 64;
            float4 v = make_float4(0.f, 0.f, 0.f, 0.f);
            if (grow < M) {
                v = *(const float4*)(A + (size_t)grow * lda + k0 + a_q);
                if (mode == 0) {
                    if (v.x == 0.f) v.x = me[k0 + a_q + 0];
                    if (v.y == 0.f) v.y = me[k0 + a_q + 1];
                    if (v.z == 0.f) v.z = me[k0 + a_q + 2];
                    if (v.w == 0.f) v.w = me[k0 + a_q + 3];
                }
            }
            pa[it] = v;
            pb[it] = *(const float4*)(B + (size_t)(k0 + b_kr + it * 8) * 128 + b_c4);
        }
    };

    auto split_store = [&]() {
#pragma unroll
        for (int it = 0; it < 2; it++) {
            float xs[4] = {pa[it].x, pa[it].y, pa[it].z, pa[it].w};
            uint32_t h[4], l[4];
#pragma unroll
            for (int i = 0; i < 4; i++) {
                h[i] = f2tf(xs[i]);
                l[i] = f2tf(xs[i] - __uint_as_float(h[i]));
            }
            int rr = a_row + it * 64;
            *(uint4*)&Ahi[rr][a_q] = make_uint4(h[0], h[1], h[2], h[3]);
            *(uint4*)&Alo[rr][a_q] = make_uint4(l[0], l[1], l[2], l[3]);

            float ys[4] = {pb[it].x, pb[it].y, pb[it].z, pb[it].w};
#pragma unroll
            for (int i = 0; i < 4; i++) {
                h[i] = f2tf(ys[i]);
                l[i] = f2tf(ys[i] - __uint_as_float(h[i]));
            }
            int kk = b_kr + it * 8;
            *(uint4*)&Bhi[kk][b_c4] = make_uint4(h[0], h[1], h[2], h[3]);
            *(uint4*)&Blo[kk][b_c4] = make_uint4(l[0], l[1], l[2], l[3]);
        }
    };

    prefetch(0);
    for (int k0 = 0; k0 < K; k0 += 16) {
        split_store();
        __syncthreads();
        if (k0 + 16 < K) prefetch(k0 + 16);
#pragma unroll
        for (int s = 0; s < 2; s++) {
            const int kb = s * 8;
            uint32_t af[4][4], al[4][4];
#pragma unroll
            for (int m = 0; m < 4; m++) {
                int r0 = wr * 64 + m * 16 + (lane >> 2);
                int cc = kb + (lane & 3);
                af[m][0] = Ahi[r0][cc];
                af[m][1] = Ahi[r0 + 8][cc];
                af[m][2] = Ahi[r0][cc + 4];
                af[m][3] = Ahi[r0 + 8][cc + 4];
                al[m][0] = Alo[r0][cc];
                al[m][1] = Alo[r0 + 8][cc];
                al[m][2] = Alo[r0][cc + 4];
                al[m][3] = Alo[r0 + 8][cc + 4];
            }
#pragma unroll
            for (int n = 0; n < 4; n++) {
                int cb = wc * 32 + n * 8 + (lane >> 2);
                int kk = kb + (lane & 3);
                uint32_t bh0 = Bhi[kk][cb], bh1 = Bhi[kk + 4][cb];
                uint32_t bl0 = Blo[kk][cb], bl1 = Blo[kk + 4][cb];
#pragma unroll
                for (int m = 0; m < 4; m++) {
                    MMA_OP(d[m][n], af[m], bh0, bh1);
                    MMA_OP(d[m][n], al[m], bh0, bh1);
                    MMA_OP(d[m][n], af[m], bl0, bl1);
                }
            }
        }
        __syncthreads();
    }

    // epilogue
#pragma unroll
    for (int m = 0; m < 4; m++) {
        int r = rowBase + wr * 64 + m * 16 + (lane >> 2);
#pragma unroll
        for (int n = 0; n < 4; n++) {
            int cc = wc * 32 + n * 8 + ((lane & 3) << 1);
            if (r < M)
                *(float2*)(Y + (size_t)r * 256 + cc) = make_float2(d[m][n][0], d[m][n][1]);
            if (r + 8 < M)
                *(float2*)(Y + (size_t)(r + 8) * 256 + cc) = make_float2(d[m][n][2], d[m][n][3]);
        }
    }
}

// ---------------- CSR gather + fused GIN epilogue ----------------
__global__ __launch_bounds__(256) void gather_kernel(
    const float* __restrict__ Y, float* __restrict__ H,
    const float* __restrict__ be, const float* __restrict__ bc,
    const float* __restrict__ epe, const float* __restrict__ epc, int Nn)
{
    const unsigned FULL = 0xffffffffu;
    int gwarp = (blockIdx.x * 256 + threadIdx.x) >> 5;
    int lane = threadIdx.x & 31;
    if (gwarp >= Nn) return;

    int beg = g_rowptr[gwarp];
    int end = g_rowptr[gwarp + 1];
    int j0 = lane * 8;

    float acc[8];
#pragma unroll
    for (int i = 0; i < 8; i++) acc[i] = 0.f;

    for (int base = beg; base < end; base += 32) {
        int idx = base + lane;
        int sl = (idx < end) ? g_csrc[idx] : 0;
        int cnt = end - base;
        if (cnt > 32) cnt = 32;
        int j = 0;
        for (; j + 1 < cnt; j += 2) {
            int s0 = __shfl_sync(FULL, sl, j);
            int s1 = __shfl_sync(FULL, sl, j + 1);
            const float* p0 = Y + (size_t)s0 * 256 + j0;
            const float* p1 = Y + (size_t)s1 * 256 + j0;
            float4 a0 = *(const float4*)p0;
            float4 a1 = *(const float4*)(p0 + 4);
            float4 c0 = *(const float4*)p1;
            float4 c1 = *(const float4*)(p1 + 4);
            acc[0] += a0.x + c0.x; acc[1] += a0.y + c0.y;
            acc[2] += a0.z + c0.z; acc[3] += a0.w + c0.w;
            acc[4] += a1.x + c1.x; acc[5] += a1.y + c1.y;
            acc[6] += a1.z + c1.z; acc[7] += a1.w + c1.w;
        }
        if (j < cnt) {
            int s0 = __shfl_sync(FULL, sl, j);
            const float* p0 = Y + (size_t)s0 * 256 + j0;
            float4 a0 = *(const float4*)p0;
            float4 a1 = *(const float4*)(p0 + 4);
            acc[0] += a0.x; acc[1] += a0.y; acc[2] += a0.z; acc[3] += a0.w;
            acc[4] += a1.x; acc[5] += a1.y; acc[6] += a1.z; acc[7] += a1.w;
        }
    }

    float fac;
    const float* bb;
    if (j0 < 128) { fac = 2.f + *epe; bb = be + j0; }
    else          { fac = 2.f + *epc; bb = bc + (j0 - 128); }

    const float* py = Y + (size_t)gwarp * 256 + j0;
    float4 y0 = *(const float4*)py;
    float4 y1 = *(const float4*)(py + 4);
    float4 o0, o1;
    o0.x = lrelu(fmaf(y0.x, fac, acc[0]) + bb[0]);
    o0.y = lrelu(fmaf(y0.y, fac, acc[1]) + bb[1]);
    o0.z = lrelu(fmaf(y0.z, fac, acc[2]) + bb[2]);
    o0.w = lrelu(fmaf(y0.w, fac, acc[3]) + bb[3]);
    o1.x = lrelu(fmaf(y1.x, fac, acc[4]) + bb[4]);
    o1.y = lrelu(fmaf(y1.y, fac, acc[5]) + bb[5]);
    o1.z = lrelu(fmaf(y1.z, fac, acc[6]) + bb[6]);
    o1.w = lrelu(fmaf(y1.w, fac, acc[7]) + bb[7]);
    float* ph = H + (size_t)gwarp * 256 + j0;
    *(float4*)ph = o0;
    *(float4*)(ph + 4) = o1;
}

// ---------------- output head ----------------
__global__ __launch_bounds__(256) void out_kernel(
    const float* __restrict__ H,
    const float* __restrict__ Wm, const float* __restrict__ bm,
    float* __restrict__ out, int M)
{
    __shared__ float sW[2048];
    __shared__ float sb[8];
    for (int i = threadIdx.x; i < 2048; i += 256) sW[i] = Wm[i];
    if (threadIdx.x < 8) sb[threadIdx.x] = bm[threadIdx.x];
    __syncthreads();

    int gwarp = (blockIdx.x * 256 + threadIdx.x) >> 5;
    int lane = threadIdx.x & 31;
    if (gwarp >= M) return;
    int j0 = lane * 8;
    const float* ph = H + (size_t)gwarp * 256 + j0;
    float4 h0 = *(const float4*)ph;
    float4 h1 = *(const float4*)(ph + 4);
    float hv[8] = {h0.x, h0.y, h0.z, h0.w, h1.x, h1.y, h1.z, h1.w};

    float acc[8];
#pragma unroll
    for (int n = 0; n < 8; n++) acc[n] = 0.f;
#pragma unroll
    for (int jj = 0; jj < 8; jj++) {
        const float* w = &sW[(size_t)(j0 + jj) * 8];
#pragma unroll
        for (int n = 0; n < 8; n++) acc[n] += hv[jj] * w[n];
    }
#pragma unroll
    for (int off = 16; off >= 1; off >>= 1)
#pragma unroll
        for (int n = 0; n < 8; n++)
            acc[n] += __shfl_xor_sync(0xffffffffu, acc[n], off);
    if (lane == 0) {
#pragma unroll
        for (int n = 0; n < 8; n++)
            out[(size_t)gwarp * 8 + n] = lrelu(acc[n] + sb[n]);
    }
}

// ---------------- central MLP ----------------
__global__ __launch_bounds__(256) void central_kernel(
    const float* __restrict__ out, const int* __restrict__ cidx,
    const float* __restrict__ Wp1, const float* __restrict__ bp1,
    const float* __restrict__ Wp2, const float* __restrict__ bp2,
    float* __restrict__ logits, int C)
{
    __shared__ float s1[1024];
    __shared__ float sb1[128];
    __shared__ float s2[1024];
    __shared__ float sb2[8];
    for (int i = threadIdx.x; i < 1024; i += 256) { s1[i] = Wp1[i]; s2[i] = Wp2[i]; }
    if (threadIdx.x < 128) sb1[threadIdx.x] = bp1[threadIdx.x];
    if (threadIdx.x < 8) sb2[threadIdx.x] = bp2[threadIdx.x];
    __syncthreads();

    int t = blockIdx.x * 256 + threadIdx.x;
    if (t >= C) return;
    int ci = cidx[t];
    float g[8];
#pragma unroll
    for (int k = 0; k < 8; k++) g[k] = out[(size_t)ci * 8 + k];
    float acc[8];
#pragma unroll
    for (int m = 0; m < 8; m++) acc[m] = sb2[m];
    for (int n = 0; n < 128; n++) {
        float tn = sb1[n];
#pragma unroll
        for (int k = 0; k < 8; k++) tn += g[k] * s1[k * 128 + n];
        tn = fmaxf(tn, 0.f);
#pragma unroll
        for (int m = 0; m < 8; m++) acc[m] += tn * s2[n * 8 + m];
    }
#pragma unroll
    for (int m = 0; m < 8; m++) logits[(size_t)t * 8 + m] = acc[m];
}

extern "C" void kernel_launch(void* const* d_in, const int* in_sizes, int n_in,
                              void* d_out, int out_size)
{
    const float* x    = (const float*)d_in[0];
    const float* c    = (const float*)d_in[1];
    const int*   ei   = (const int*)d_in[2];
    const int*   cidx = (const int*)d_in[3];
    const float* me_x = (const float*)d_in[4];
    const float* me_c = (const float*)d_in[5];
    const float* W1e  = (const float*)d_in[6];
    const float* b1e  = (const float*)d_in[7];
    const float* e1e  = (const float*)d_in[8];
    const float* W2e  = (const float*)d_in[9];
    const float* b2e  = (const float*)d_in[10];
    const float* e2e  = (const float*)d_in[11];
    const float* W1c  = (const float*)d_in[12];
    const float* b1c  = (const float*)d_in[13];
    const float* e1c  = (const float*)d_in[14];
    const float* W2c  = (const float*)d_in[15];
    const float* b2c  = (const float*)d_in[16];
    const float* e2c  = (const float*)d_in[17];
    const float* Wm   = (const float*)d_in[18];
    const float* bm   = (const float*)d_in[19];
    const float* Wp1  = (const float*)d_in[20];
    const float* bp1  = (const float*)d_in[21];
    const float* Wp2  = (const float*)d_in[22];
    const float* bp2  = (const float*)d_in[23];

    const int Nn = in_sizes[0] / NFE;       // 50000
    const int E  = in_sizes[2] / 2;         // 800000
    const int C  = in_sizes[3];             // 512

    float *Y1, *H1, *Y2, *H2;
    cudaGetSymbolAddress((void**)&Y1, g_Y1);
    cudaGetSymbolAddress((void**)&H1, g_H1);
    cudaGetSymbolAddress((void**)&Y2, g_Y2);
    cudaGetSymbolAddress((void**)&H2, g_H2);

    float* out_p    = (float*)d_out;              // [N, 8]
    float* logits_p = (float*)d_out + (size_t)Nn * 8;

    // CSR build (by dst)
    zero_cnt_kernel<<<(Nn + 255) / 256, 256>>>(Nn);
    hist_kernel<<<(E + 255) / 256, 256>>>(ei, E);
    scan_kernel<<<1, 1024>>>(Nn);
    fill_kernel<<<(E + 255) / 256, 256>>>(ei, E);

    int gridM = (Nn + 127) / 128;
    int gridW = (Nn * 32 + 255) / 256;

    // layer-1 projections (matmul-first)
    gemm_tf32_kernel<<<gridM, 256>>>(x, me_x, W1e, Y1, Nn, NFE, NFE, 0);
    gemm_tf32_kernel<<<gridM, 256>>>(c, me_c, W1c, Y1 + 128, Nn, NFC, NFC, 0);

    // layer-1 aggregation + epilogue -> H1
    gather_kernel<<<gridW, 256>>>(Y1, H1, b1e, b1c, e1e, e1c, Nn);

    // layer-2 projections (plain)
    gemm_tf32_kernel<<<gridM, 256>>>(H1, nullptr, W2e, Y2, Nn, 128, 256, 2);
    gemm_tf32_kernel<<<gridM, 256>>>(H1 + 128, nullptr, W2c, Y2 + 128, Nn, 128, 256, 2);

    // layer-2 aggregation + epilogue -> H2
    gather_kernel<<<gridW, 256>>>(Y2, H2, b2e, b2c, e2e, e2c, Nn);

    // output head
    out_kernel<<<gridW, 256>>>(H2, Wm, bm, out_p, Nn);

    // central MLP
    central_kernel<<<(C + 255) / 256, 256>>>(out_p, cidx, Wp1, bp1, Wp2, bp2, logits_p, C);
}

// round 4
// speedup vs baseline: 1.5339x; 1.0908x over previous
#include <cuda_runtime.h>
#include <cuda_bf16.h>
#include <cstdint>

#define NFE 256
#define NFC 128
#define MAXN 50000
#define MAXE 800000

// Scratch buffers
__device__ float g_Y1[(size_t)MAXN * 256];
__device__ float g_H1[(size_t)MAXN * 256];
__device__ float g_Y2[(size_t)MAXN * 256];
__device__ float g_H2[(size_t)MAXN * 256];
__device__ int g_cnt[MAXN];
__device__ int g_fill[MAXN];
__device__ int g_rowptr[MAXN + 1];
__device__ int g_csrc[MAXE];

__device__ __forceinline__ float lrelu(float v) { return v > 0.f ? v : 0.2f * v; }

// split two floats into bf16x2 hi word + bf16x2 lo word
__device__ __forceinline__ void split2(float x, float y, uint32_t& hi, uint32_t& lo) {
    __nv_bfloat162 h = __float22bfloat162_rn(make_float2(x, y));
    hi = *reinterpret_cast<uint32_t*>(&h);
    float rx = x - __bfloat162float(h.x);
    float ry = y - __bfloat162float(h.y);
    __nv_bfloat162 l = __float22bfloat162_rn(make_float2(rx, ry));
    lo = *reinterpret_cast<uint32_t*>(&l);
}

// ---------------- CSR build ----------------
__global__ void zero_cnt_kernel(int n) {
    int i = blockIdx.x * blockDim.x + threadIdx.x;
    if (i < n) g_cnt[i] = 0;
}

__global__ void hist_kernel(const int* __restrict__ ei, int E) {
    int e = blockIdx.x * blockDim.x + threadIdx.x;
    if (e < E) atomicAdd(&g_cnt[ei[E + e]], 1);
}

__global__ __launch_bounds__(1024) void scan_kernel(int N) {
    __shared__ int ssum[1024];
    int tid = threadIdx.x;
    int chunk = (N + 1023) / 1024;
    int lo = tid * chunk;
    int hi = lo + chunk;
    if (hi > N) hi = N;
    int s = 0;
    for (int i = lo; i < hi; i++) s += g_cnt[i];
    ssum[tid] = s;
    __syncthreads();
    for (int off = 1; off < 1024; off <<= 1) {
        int t = (tid >= off) ? ssum[tid - off] : 0;
        __syncthreads();
        ssum[tid] += t;
        __syncthreads();
    }
    int run = ssum[tid] - s;
    for (int i = lo; i < hi; i++) {
        g_rowptr[i] = run;
        g_fill[i] = run;
        run += g_cnt[i];
    }
    if (tid == 1023) g_rowptr[N] = ssum[1023];
}

__global__ void fill_kernel(const int* __restrict__ ei, int E) {
    int e = blockIdx.x * blockDim.x + threadIdx.x;
    if (e < E) {
        int s = ei[e];
        int d = ei[E + e];
        int pos = atomicAdd(&g_fill[d], 1);
        g_csrc[pos] = s;
    }
}

// ---------------- BF16x3 tensor-core GEMM ----------------
// Y[rows, 0:128] (col offset folded into Y; Y row stride 256) = Amod @ B
// mode 0: Amod = where(A==0, me[k], A);  mode 2: Amod = A
#define MMA_BF16(D, Areg, B0, B1)                                            \
    asm volatile("mma.sync.aligned.m16n8k16.row.col.f32.bf16.bf16.f32 "      \
                 "{%0,%1,%2,%3},{%4,%5,%6,%7},{%8,%9},{%0,%1,%2,%3};"        \
                 : "+f"(D[0]), "+f"(D[1]), "+f"(D[2]), "+f"(D[3])            \
                 : "r"(Areg[0]), "r"(Areg[1]), "r"(Areg[2]), "r"(Areg[3]),   \
                   "r"(B0), "r"(B1))

__global__ __launch_bounds__(256, 2) void gemm_bf16_kernel(
    const float* __restrict__ A, const float* __restrict__ me,
    const float* __restrict__ B, float* __restrict__ Y,
    int M, int K, int lda, int mode)
{
    // word = bf16x2 along k. A: 128 rows x 8 kp-words (stride 12 for bank spread)
    __shared__ uint32_t Ahi[128][12], Alo[128][12];
    // B: 8 kp-words x 128 cols (stride 132)
    __shared__ uint32_t Bhi[8][132], Blo[8][132];

    const int tid = threadIdx.x;
    const int lane = tid & 31;
    const int warp = tid >> 5;
    const int wr = warp & 1;    // warp row (64 rows each)
    const int wc = warp >> 1;   // warp col (32 cols each)
    const int rowBase = blockIdx.x * 128;

    float d[4][4][4];
#pragma unroll
    for (int m = 0; m < 4; m++)
#pragma unroll
        for (int n = 0; n < 4; n++)
#pragma unroll
            for (int r = 0; r < 4; r++) d[m][n][r] = 0.f;

    // A-load coords: rows tid>>2 and +64, k-quad (tid&3)*4
    const int a_row = tid >> 2;
    const int a_kq = (tid & 3) << 2;
    // B-load coords: k-pair tid>>5 (rows 2kp, 2kp+1), cols (lane)*4
    const int b_kp = tid >> 5;
    const int b_c4 = lane << 2;

    float4 pa[2], pbe, pbo;

    auto prefetch = [&](int k0) {
#pragma unroll
        for (int it = 0; it < 2; it++) {
            int grow = rowBase + a_row + it * 64;
            float4 v = make_float4(0.f, 0.f, 0.f, 0.f);
            if (grow < M) {
                v = *(const float4*)(A + (size_t)grow * lda + k0 + a_kq);
                if (mode == 0) {
                    if (v.x == 0.f) v.x = me[k0 + a_kq + 0];
                    if (v.y == 0.f) v.y = me[k0 + a_kq + 1];
                    if (v.z == 0.f) v.z = me[k0 + a_kq + 2];
                    if (v.w == 0.f) v.w = me[k0 + a_kq + 3];
                }
            }
            pa[it] = v;
        }
        pbe = *(const float4*)(B + (size_t)(k0 + 2 * b_kp) * 128 + b_c4);
        pbo = *(const float4*)(B + (size_t)(k0 + 2 * b_kp + 1) * 128 + b_c4);
    };

    auto split_store = [&]() {
        const int kp0 = (tid & 3) << 1;
#pragma unroll
        for (int it = 0; it < 2; it++) {
            int rr = a_row + it * 64;
            uint32_t h0, l0, h1, l1;
            split2(pa[it].x, pa[it].y, h0, l0);
            split2(pa[it].z, pa[it].w, h1, l1);
            Ahi[rr][kp0] = h0; Ahi[rr][kp0 + 1] = h1;
            Alo[rr][kp0] = l0; Alo[rr][kp0 + 1] = l1;
        }
        // B: word c = (even[c], odd[c])  -- pack along k
        float ev[4] = {pbe.x, pbe.y, pbe.z, pbe.w};
        float od[4] = {pbo.x, pbo.y, pbo.z, pbo.w};
#pragma unroll
        for (int i = 0; i < 4; i++) {
            uint32_t h, l;
            split2(ev[i], od[i], h, l);
            Bhi[b_kp][b_c4 + i] = h;
            Blo[b_kp][b_c4 + i] = l;
        }
    };

    prefetch(0);
    for (int k0 = 0; k0 < K; k0 += 16) {
        split_store();
        __syncthreads();
        if (k0 + 16 < K) prefetch(k0 + 16);

        uint32_t ah[4][4], al[4][4];
        const int kp = lane & 3;
#pragma unroll
        for (int m = 0; m < 4; m++) {
            int r0 = wr * 64 + m * 16 + (lane >> 2);
            ah[m][0] = Ahi[r0][kp];
            ah[m][1] = Ahi[r0 + 8][kp];
            ah[m][2] = Ahi[r0][kp + 4];
            ah[m][3] = Ahi[r0 + 8][kp + 4];
            al[m][0] = Alo[r0][kp];
            al[m][1] = Alo[r0 + 8][kp];
            al[m][2] = Alo[r0][kp + 4];
            al[m][3] = Alo[r0 + 8][kp + 4];
        }
#pragma unroll
        for (int n = 0; n < 4; n++) {
            int cb = wc * 32 + n * 8 + (lane >> 2);
            uint32_t bh0 = Bhi[kp][cb], bh1 = Bhi[kp + 4][cb];
            uint32_t bl0 = Blo[kp][cb], bl1 = Blo[kp + 4][cb];
#pragma unroll
            for (int m = 0; m < 4; m++) {
                MMA_BF16(d[m][n], ah[m], bh0, bh1);
                MMA_BF16(d[m][n], al[m], bh0, bh1);
                MMA_BF16(d[m][n], ah[m], bl0, bl1);
            }
        }
        __syncthreads();
    }

    // epilogue
#pragma unroll
    for (int m = 0; m < 4; m++) {
        int r = rowBase + wr * 64 + m * 16 + (lane >> 2);
#pragma unroll
        for (int n = 0; n < 4; n++) {
            int cc = wc * 32 + n * 8 + ((lane & 3) << 1);
            if (r < M)
                *(float2*)(Y + (size_t)r * 256 + cc) = make_float2(d[m][n][0], d[m][n][1]);
            if (r + 8 < M)
                *(float2*)(Y + (size_t)(r + 8) * 256 + cc) = make_float2(d[m][n][2], d[m][n][3]);
        }
    }
}

// ---------------- CSR gather + fused GIN epilogue ----------------
__global__ __launch_bounds__(256) void gather_kernel(
    const float* __restrict__ Y, float* __restrict__ H,
    const float* __restrict__ be, const float* __restrict__ bc,
    const float* __restrict__ epe, const float* __restrict__ epc, int Nn)
{
    const unsigned FULL = 0xffffffffu;
    int gwarp = (blockIdx.x * 256 + threadIdx.x) >> 5;
    int lane = threadIdx.x & 31;
    if (gwarp >= Nn) return;

    int beg = g_rowptr[gwarp];
    int end = g_rowptr[gwarp + 1];
    int j0 = lane * 8;

    float acc[8];
#pragma unroll
    for (int i = 0; i < 8; i++) acc[i] = 0.f;

    for (int base = beg; base < end; base += 32) {
        int idx = base + lane;
        int sl = (idx < end) ? g_csrc[idx] : 0;
        int cnt = end - base;
        if (cnt > 32) cnt = 32;
        int j = 0;
        for (; j + 3 < cnt; j += 4) {
            int s0 = __shfl_sync(FULL, sl, j);
            int s1 = __shfl_sync(FULL, sl, j + 1);
            int s2 = __shfl_sync(FULL, sl, j + 2);
            int s3 = __shfl_sync(FULL, sl, j + 3);
            const float* p0 = Y + (size_t)s0 * 256 + j0;
            const float* p1 = Y + (size_t)s1 * 256 + j0;
            const float* p2 = Y + (size_t)s2 * 256 + j0;
            const float* p3 = Y + (size_t)s3 * 256 + j0;
            float4 a0 = *(const float4*)p0;
            float4 a1 = *(const float4*)(p0 + 4);
            float4 b0 = *(const float4*)p1;
            float4 b1 = *(const float4*)(p1 + 4);
            float4 c0 = *(const float4*)p2;
            float4 c1 = *(const float4*)(p2 + 4);
            float4 e0 = *(const float4*)p3;
            float4 e1 = *(const float4*)(p3 + 4);
            acc[0] += (a0.x + b0.x) + (c0.x + e0.x);
            acc[1] += (a0.y + b0.y) + (c0.y + e0.y);
            acc[2] += (a0.z + b0.z) + (c0.z + e0.z);
            acc[3] += (a0.w + b0.w) + (c0.w + e0.w);
            acc[4] += (a1.x + b1.x) + (c1.x + e1.x);
            acc[5] += (a1.y + b1.y) + (c1.y + e1.y);
            acc[6] += (a1.z + b1.z) + (c1.z + e1.z);
            acc[7] += (a1.w + b1.w) + (c1.w + e1.w);
        }
        for (; j < cnt; j++) {
            int s0 = __shfl_sync(FULL, sl, j);
            const float* p0 = Y + (size_t)s0 * 256 + j0;
            float4 a0 = *(const float4*)p0;
            float4 a1 = *(const float4*)(p0 + 4);
            acc[0] += a0.x; acc[1] += a0.y; acc[2] += a0.z; acc[3] += a0.w;
            acc[4] += a1.x; acc[5] += a1.y; acc[6] += a1.z; acc[7] += a1.w;
        }
    }

    float fac;
    const float* bb;
    if (j0 < 128) { fac = 2.f + *epe; bb = be + j0; }
    else          { fac = 2.f + *epc; bb = bc + (j0 - 128); }

    const float* py = Y + (size_t)gwarp * 256 + j0;
    float4 y0 = *(const float4*)py;
    float4 y1 = *(const float4*)(py + 4);
    float4 o0, o1;
    o0.x = lrelu(fmaf(y0.x, fac, acc[0]) + bb[0]);
    o0.y = lrelu(fmaf(y0.y, fac, acc[1]) + bb[1]);
    o0.z = lrelu(fmaf(y0.z, fac, acc[2]) + bb[2]);
    o0.w = lrelu(fmaf(y0.w, fac, acc[3]) + bb[3]);
    o1.x = lrelu(fmaf(y1.x, fac, acc[4]) + bb[4]);
    o1.y = lrelu(fmaf(y1.y, fac, acc[5]) + bb[5]);
    o1.z = lrelu(fmaf(y1.z, fac, acc[6]) + bb[6]);
    o1.w = lrelu(fmaf(y1.w, fac, acc[7]) + bb[7]);
    float* ph = H + (size_t)gwarp * 256 + j0;
    *(float4*)ph = o0;
    *(float4*)(ph + 4) = o1;
}

// ---------------- output head ----------------
__global__ __launch_bounds__(256) void out_kernel(
    const float* __restrict__ H,
    const float* __restrict__ Wm, const float* __restrict__ bm,
    float* __restrict__ out, int M)
{
    __shared__ float sW[2048];
    __shared__ float sb[8];
    for (int i = threadIdx.x; i < 2048; i += 256) sW[i] = Wm[i];
    if (threadIdx.x < 8) sb[threadIdx.x] = bm[threadIdx.x];
    __syncthreads();

    int gwarp = (blockIdx.x * 256 + threadIdx.x) >> 5;
    int lane = threadIdx.x & 31;
    if (gwarp >= M) return;
    int j0 = lane * 8;
    const float* ph = H + (size_t)gwarp * 256 + j0;
    float4 h0 = *(const float4*)ph;
    float4 h1 = *(const float4*)(ph + 4);
    float hv[8] = {h0.x, h0.y, h0.z, h0.w, h1.x, h1.y, h1.z, h1.w};

    float acc[8];
#pragma unroll
    for (int n = 0; n < 8; n++) acc[n] = 0.f;
#pragma unroll
    for (int jj = 0; jj < 8; jj++) {
        const float* w = &sW[(size_t)(j0 + jj) * 8];
#pragma unroll
        for (int n = 0; n < 8; n++) acc[n] += hv[jj] * w[n];
    }
#pragma unroll
    for (int off = 16; off >= 1; off >>= 1)
#pragma unroll
        for (int n = 0; n < 8; n++)
            acc[n] += __shfl_xor_sync(0xffffffffu, acc[n], off);
    if (lane == 0) {
#pragma unroll
        for (int n = 0; n < 8; n++)
            out[(size_t)gwarp * 8 + n] = lrelu(acc[n] + sb[n]);
    }
}

// ---------------- central MLP ----------------
__global__ __launch_bounds__(256) void central_kernel(
    const float* __restrict__ out, const int* __restrict__ cidx,
    const float* __restrict__ Wp1, const float* __restrict__ bp1,
    const float* __restrict__ Wp2, const float* __restrict__ bp2,
    float* __restrict__ logits, int C)
{
    __shared__ float s1[1024];
    __shared__ float sb1[128];
    __shared__ float s2[1024];
    __shared__ float sb2[8];
    for (int i = threadIdx.x; i < 1024; i += 256) { s1[i] = Wp1[i]; s2[i] = Wp2[i]; }
    if (threadIdx.x < 128) sb1[threadIdx.x] = bp1[threadIdx.x];
    if (threadIdx.x < 8) sb2[threadIdx.x] = bp2[threadIdx.x];
    __syncthreads();

    int t = blockIdx.x * 256 + threadIdx.x;
    if (t >= C) return;
    int ci = cidx[t];
    float g[8];
#pragma unroll
    for (int k = 0; k < 8; k++) g[k] = out[(size_t)ci * 8 + k];
    float acc[8];
#pragma unroll
    for (int m = 0; m < 8; m++) acc[m] = sb2[m];
    for (int n = 0; n < 128; n++) {
        float tn = sb1[n];
#pragma unroll
        for (int k = 0; k < 8; k++) tn += g[k] * s1[k * 128 + n];
        tn = fmaxf(tn, 0.f);
#pragma unroll
        for (int m = 0; m < 8; m++) acc[m] += tn * s2[n * 8 + m];
    }
#pragma unroll
    for (int m = 0; m < 8; m++) logits[(size_t)t * 8 + m] = acc[m];
}

extern "C" void kernel_launch(void* const* d_in, const int* in_sizes, int n_in,
                              void* d_out, int out_size)
{
    const float* x    = (const float*)d_in[0];
    const float* c    = (const float*)d_in[1];
    const int*   ei   = (const int*)d_in[2];
    const int*   cidx = (const int*)d_in[3];
    const float* me_x = (const float*)d_in[4];
    const float* me_c = (const float*)d_in[5];
    const float* W1e  = (const float*)d_in[6];
    const float* b1e  = (const float*)d_in[7];
    const float* e1e  = (const float*)d_in[8];
    const float* W2e  = (const float*)d_in[9];
    const float* b2e  = (const float*)d_in[10];
    const float* e2e  = (const float*)d_in[11];
    const float* W1c  = (const float*)d_in[12];
    const float* b1c  = (const float*)d_in[13];
    const float* e1c  = (const float*)d_in[14];
    const float* W2c  = (const float*)d_in[15];
    const float* b2c  = (const float*)d_in[16];
    const float* e2c  = (const float*)d_in[17];
    const float* Wm   = (const float*)d_in[18];
    const float* bm   = (const float*)d_in[19];
    const float* Wp1  = (const float*)d_in[20];
    const float* bp1  = (const float*)d_in[21];
    const float* Wp2  = (const float*)d_in[22];
    const float* bp2  = (const float*)d_in[23];

    const int Nn = in_sizes[0] / NFE;       // 50000
    const int E  = in_sizes[2] / 2;         // 800000
    const int C  = in_sizes[3];             // 512

    float *Y1, *H1, *Y2, *H2;
    cudaGetSymbolAddress((void**)&Y1, g_Y1);
    cudaGetSymbolAddress((void**)&H1, g_H1);
    cudaGetSymbolAddress((void**)&Y2, g_Y2);
    cudaGetSymbolAddress((void**)&H2, g_H2);

    float* out_p    = (float*)d_out;              // [N, 8]
    float* logits_p = (float*)d_out + (size_t)Nn * 8;

    // CSR build (by dst)
    zero_cnt_kernel<<<(Nn + 255) / 256, 256>>>(Nn);
    hist_kernel<<<(E + 255) / 256, 256>>>(ei, E);
    scan_kernel<<<1, 1024>>>(Nn);
    fill_kernel<<<(E + 255) / 256, 256>>>(ei, E);

    int gridM = (Nn + 127) / 128;
    int gridW = (Nn * 32 + 255) / 256;

    // layer-1 projections (matmul-first)
    gemm_bf16_kernel<<<gridM, 256>>>(x, me_x, W1e, Y1, Nn, NFE, NFE, 0);
    gemm_bf16_kernel<<<gridM, 256>>>(c, me_c, W1c, Y1 + 128, Nn, NFC, NFC, 0);

    // layer-1 aggregation + epilogue -> H1
    gather_kernel<<<gridW, 256>>>(Y1, H1, b1e, b1c, e1e, e1c, Nn);

    // layer-2 projections (plain)
    gemm_bf16_kernel<<<gridM, 256>>>(H1, nullptr, W2e, Y2, Nn, 128, 256, 2);
    gemm_bf16_kernel<<<gridM, 256>>>(H1 + 128, nullptr, W2c, Y2 + 128, Nn, 128, 256, 2);

    // layer-2 aggregation + epilogue -> H2
    gather_kernel<<<gridW, 256>>>(Y2, H2, b2e, b2c, e2e, e2c, Nn);

    // output head
    out_kernel<<<gridW, 256>>>(H2, Wm, bm, out_p, Nn);

    // central MLP
    central_kernel<<<(C + 255) / 256, 256>>>(out_p, cidx, Wp1, bp1, Wp2, bp2, logits_p, C);
}